// round 1
// baseline (speedup 1.0000x reference)
#include <cuda_runtime.h>
#include <math.h>

#define BROWS 8192
#define DIM   256
static __device__ __constant__ float kEPS = 1e-8f;

// scratch (device globals: no allocation allowed)
__device__ float              g_xn[BROWS * DIM];     // normalized rows, 8 MB
__device__ unsigned long long g_best[BROWS];         // packed (orderable float, ~idx)
__device__ float              g_logd[BROWS];

// ---------------------------------------------------------------------------
// order-preserving pack: larger dot => larger u64; on equal dot, SMALLER index
// => larger u64 (matches jnp.argmax first-occurrence tie-break).
__device__ __forceinline__ unsigned long long pack_vi(float v, int idx) {
    unsigned int u = __float_as_uint(v);
    u = (u & 0x80000000u) ? ~u : (u | 0x80000000u);
    return ((unsigned long long)u << 32) | (unsigned long long)(0xFFFFFFFFu - (unsigned int)idx);
}
__device__ __forceinline__ int unpack_idx(unsigned long long p) {
    return (int)(0xFFFFFFFFu - (unsigned int)(p & 0xFFFFFFFFu));
}

// ---------------------------------------------------------------------------
// Kernel 1: normalize first BROWS rows of student. 64 threads/row (float4).
__global__ void koleo_normalize(const float* __restrict__ x) {
    int row  = blockIdx.x;
    int lane = threadIdx.x;          // 0..63
    float4 v = ((const float4*)(x + (size_t)row * DIM))[lane];
    float s = v.x * v.x + v.y * v.y + v.z * v.z + v.w * v.w;
    #pragma unroll
    for (int o = 16; o > 0; o >>= 1) s += __shfl_xor_sync(0xffffffffu, s, o);
    __shared__ float sh[2];
    if ((lane & 31) == 0) sh[lane >> 5] = s;
    __syncthreads();
    float inv = 1.0f / fmaxf(sqrtf(sh[0] + sh[1]), kEPS);
    v.x *= inv; v.y *= inv; v.z *= inv; v.w *= inv;
    ((float4*)(g_xn + (size_t)row * DIM))[lane] = v;
}

// Kernel 2: zero the packed best array (floor of packed domain).
__global__ void koleo_init_best() {
    int i = blockIdx.x * blockDim.x + threadIdx.x;
    if (i < BROWS) g_best[i] = 0ull;
}

// ---------------------------------------------------------------------------
// Kernel 3: tiled GEMM-argmax. BM=BN=128, BK=16, 256 threads, 8x8 per thread.
// grid = (BROWS/BM, NSPLIT); each block scans a 1/NSPLIT slice of columns and
// atomically merges per-row (max, argmax) into g_best.
#define BM 128
#define BN 128
#define BKK 16
#define NSPLIT 8
#define JCHUNK (BROWS / NSPLIT)

__global__ __launch_bounds__(256) void koleo_argmax() {
    __shared__ float sA[BKK][BM];
    __shared__ float sB[BKK][BN];
    __shared__ unsigned long long sred[BM][16];

    const int tid = threadIdx.x;
    const int tx  = tid & 15;        // 0..15 : column group
    const int ty  = tid >> 4;        // 0..15 : row group
    const int rowbase = blockIdx.x * BM;
    const int jstart  = blockIdx.y * JCHUNK;

    // global-load coordinates (each thread loads 8 contiguous k for one m)
    const int lm = tid >> 1;             // 0..127
    const int lk = (tid & 1) << 3;       // 0 or 8

    float bestval[8];
    int   bestidx[8];
    #pragma unroll
    for (int i = 0; i < 8; i++) { bestval[i] = -2.0f; bestidx[i] = 0; }

    for (int jb = jstart; jb < jstart + JCHUNK; jb += BN) {
        float acc[8][8];
        #pragma unroll
        for (int i = 0; i < 8; i++)
            #pragma unroll
            for (int j = 0; j < 8; j++) acc[i][j] = 0.0f;

        #pragma unroll 1
        for (int k0 = 0; k0 < DIM; k0 += BKK) {
            const float* pa = g_xn + (size_t)(rowbase + lm) * DIM + k0 + lk;
            const float* pb = g_xn + (size_t)(jb      + lm) * DIM + k0 + lk;
            float4 a0 = *(const float4*)(pa);
            float4 a1 = *(const float4*)(pa + 4);
            float4 b0 = *(const float4*)(pb);
            float4 b1 = *(const float4*)(pb + 4);
            __syncthreads();
            sA[lk + 0][lm] = a0.x; sA[lk + 1][lm] = a0.y; sA[lk + 2][lm] = a0.z; sA[lk + 3][lm] = a0.w;
            sA[lk + 4][lm] = a1.x; sA[lk + 5][lm] = a1.y; sA[lk + 6][lm] = a1.z; sA[lk + 7][lm] = a1.w;
            sB[lk + 0][lm] = b0.x; sB[lk + 1][lm] = b0.y; sB[lk + 2][lm] = b0.z; sB[lk + 3][lm] = b0.w;
            sB[lk + 4][lm] = b1.x; sB[lk + 5][lm] = b1.y; sB[lk + 6][lm] = b1.z; sB[lk + 7][lm] = b1.w;
            __syncthreads();

            #pragma unroll
            for (int k = 0; k < BKK; k++) {
                float4 A0 = *(const float4*)&sA[k][ty * 8];
                float4 A1 = *(const float4*)&sA[k][ty * 8 + 4];
                float4 B0 = *(const float4*)&sB[k][tx * 8];
                float4 B1 = *(const float4*)&sB[k][tx * 8 + 4];
                float af[8] = {A0.x, A0.y, A0.z, A0.w, A1.x, A1.y, A1.z, A1.w};
                float bf[8] = {B0.x, B0.y, B0.z, B0.w, B1.x, B1.y, B1.z, B1.w};
                #pragma unroll
                for (int i = 0; i < 8; i++)
                    #pragma unroll
                    for (int j = 0; j < 8; j++)
                        acc[i][j] = fmaf(af[i], bf[j], acc[i][j]);
            }
        }

        // fold tile into per-thread running (max, argmax); skip the diagonal.
        #pragma unroll
        for (int i = 0; i < 8; i++) {
            const int row = rowbase + ty * 8 + i;
            #pragma unroll
            for (int j = 0; j < 8; j++) {
                const int col = jb + tx * 8 + j;
                const float v = acc[i][j];
                // strict '>' keeps earliest (smallest col) on exact ties,
                // since we scan cols in increasing order within a thread.
                if (col != row && v > bestval[i]) { bestval[i] = v; bestidx[i] = col; }
            }
        }
    }

    __syncthreads();
    #pragma unroll
    for (int i = 0; i < 8; i++)
        sred[ty * 8 + i][tx] = pack_vi(bestval[i], bestidx[i]);
    __syncthreads();

    if (tid < BM) {
        unsigned long long m = sred[tid][0];
        #pragma unroll
        for (int t = 1; t < 16; t++) {
            unsigned long long c = sred[tid][t];
            if (c > m) m = c;
        }
        atomicMax(&g_best[rowbase + tid], m);
    }
}

// ---------------------------------------------------------------------------
// Kernel 4: per-row distance + log. One warp per row.
__global__ void koleo_dist() {
    int row  = blockIdx.x * 8 + (threadIdx.x >> 5);
    int lane = threadIdx.x & 31;
    int nb   = unpack_idx(g_best[row]);
    const float* xi = g_xn + (size_t)row * DIM;
    const float* xj = g_xn + (size_t)nb  * DIM;
    float s = 0.0f;
    #pragma unroll
    for (int c = lane; c < DIM; c += 32) {
        float d = xi[c] - xj[c] + kEPS;
        s = fmaf(d, d, s);
    }
    #pragma unroll
    for (int o = 16; o > 0; o >>= 1) s += __shfl_xor_sync(0xffffffffu, s, o);
    if (lane == 0) g_logd[row] = logf(sqrtf(s) + kEPS);
}

// Kernel 5: deterministic tree reduction -> scalar loss.
__global__ void koleo_reduce(float* __restrict__ out) {
    __shared__ float sh[32];
    int tid = threadIdx.x;           // 1024 threads
    float s = 0.0f;
    #pragma unroll
    for (int i = tid; i < BROWS; i += 1024) s += g_logd[i];
    #pragma unroll
    for (int o = 16; o > 0; o >>= 1) s += __shfl_xor_sync(0xffffffffu, s, o);
    if ((tid & 31) == 0) sh[tid >> 5] = s;
    __syncthreads();
    if (tid < 32) {
        float v = sh[tid];
        #pragma unroll
        for (int o = 16; o > 0; o >>= 1) v += __shfl_xor_sync(0xffffffffu, v, o);
        if (tid == 0) out[0] = -v / (float)BROWS;
    }
}

// ---------------------------------------------------------------------------
extern "C" void kernel_launch(void* const* d_in, const int* in_sizes, int n_in,
                              void* d_out, int out_size) {
    const float* student = (const float*)d_in[0];
    float* out = (float*)d_out;
    (void)in_sizes; (void)n_in; (void)out_size;

    koleo_normalize<<<BROWS, 64>>>(student);
    koleo_init_best<<<(BROWS + 255) / 256, 256>>>();
    dim3 grid(BROWS / BM, NSPLIT);
    koleo_argmax<<<grid, 256>>>();
    koleo_dist<<<BROWS / 8, 256>>>();
    koleo_reduce<<<1, 1024>>>(out);
}

// round 3
// speedup vs baseline: 7.5016x; 7.5016x over previous
#include <cuda_runtime.h>
#include <cuda_fp16.h>
#include <math.h>
#include <stdint.h>

#define BROWS 8192
#define DIM   256
#define NRB   64            // row blocks of 128
#define NCG   16            // column groups
#define TPG   4             // 128-wide col tiles per group
#define RSB   528           // smem row stride in bytes (264 halves: 512 + 16 pad)
#define ATILE (128 * RSB)   // 67584 B per tile buffer

static __device__ __constant__ float kEPS = 1e-8f;

// ------------------------- device scratch ----------------------------------
__device__ __align__(16) float  g_xn[BROWS * DIM];   // normalized fp32 (8 MB)
__device__ __align__(16) __half g_xh[BROWS * DIM];   // normalized fp16 (4 MB)
__device__ unsigned long long   g_best[BROWS];
__device__ float                g_logd[BROWS];

// ------------------------- helpers -----------------------------------------
__device__ __forceinline__ uint32_t smem_u32(const void* p) {
    uint32_t a;
    asm("{ .reg .u64 t; cvta.to.shared.u64 t, %1; cvt.u32.u64 %0, t; }" : "=r"(a) : "l"(p));
    return a;
}
__device__ __forceinline__ void ldsm4(uint32_t r[4], uint32_t a) {
    asm volatile("ldmatrix.sync.aligned.m8n8.x4.shared.b16 {%0,%1,%2,%3}, [%4];"
                 : "=r"(r[0]), "=r"(r[1]), "=r"(r[2]), "=r"(r[3]) : "r"(a));
}
__device__ __forceinline__ void mma16816(float c[4], const uint32_t a[4],
                                         uint32_t b0, uint32_t b1) {
    asm volatile("mma.sync.aligned.m16n8k16.row.col.f32.f16.f16.f32 "
                 "{%0,%1,%2,%3}, {%4,%5,%6,%7}, {%8,%9}, {%0,%1,%2,%3};"
                 : "+f"(c[0]), "+f"(c[1]), "+f"(c[2]), "+f"(c[3])
                 : "r"(a[0]), "r"(a[1]), "r"(a[2]), "r"(a[3]), "r"(b0), "r"(b1));
}
#define CP16(dst, src)  asm volatile("cp.async.cg.shared.global [%0], [%1], 16;" :: "r"(dst), "l"(src) : "memory")
#define CPCOMMIT()      asm volatile("cp.async.commit_group;" ::: "memory")
#define CPWAIT(n)       asm volatile("cp.async.wait_group %0;" :: "n"(n) : "memory")

// pack: high 32 = orderable key (dot+2 > 0, so raw float bits are monotone),
// low 32 = 8191-col (tie -> smaller col wins under u64 max).
__device__ __forceinline__ unsigned long long pack_vi(float v, int col) {
    return ((unsigned long long)__float_as_uint(v + 2.0f) << 32) |
           (unsigned)(8191 - col);
}
__device__ __forceinline__ int unpack_idx(unsigned long long p) {
    return 8191 - (int)(p & 0xFFFFFFFFull);
}

// ---------------------------------------------------------------------------
// Kernel 1: normalize rows -> fp32 scratch + fp16 copy. 64 threads/row.
__global__ void koleo_normcvt(const float* __restrict__ x) {
    int row  = blockIdx.x;
    int lane = threadIdx.x;                 // 0..63
    float4 v = ((const float4*)(x + (size_t)row * DIM))[lane];
    float s = v.x * v.x + v.y * v.y + v.z * v.z + v.w * v.w;
    #pragma unroll
    for (int o = 16; o > 0; o >>= 1) s += __shfl_xor_sync(0xffffffffu, s, o);
    __shared__ float sh[2];
    if ((lane & 31) == 0) sh[lane >> 5] = s;
    __syncthreads();
    float inv = 1.0f / fmaxf(sqrtf(sh[0] + sh[1]), kEPS);
    v.x *= inv; v.y *= inv; v.z *= inv; v.w *= inv;
    ((float4*)(g_xn + (size_t)row * DIM))[lane] = v;

    ushort4 H;
    H.x = __half_as_ushort(__float2half_rn(v.x));
    H.y = __half_as_ushort(__float2half_rn(v.y));
    H.z = __half_as_ushort(__float2half_rn(v.z));
    H.w = __half_as_ushort(__float2half_rn(v.w));
    *(ushort4*)(g_xh + (size_t)row * DIM + lane * 4) = H;
}

__global__ void koleo_init_best() {
    int i = blockIdx.x * blockDim.x + threadIdx.x;
    if (i < BROWS) g_best[i] = 0ull;
}

// ---------------------------------------------------------------------------
// async copy one 128x256 fp16 tile into padded smem
__device__ __forceinline__ void load_tile_async(uint32_t sdst,
                                                const __half* __restrict__ src,
                                                int tid) {
    #pragma unroll
    for (int i = 0; i < 16; i++) {
        int flat = tid + i * 256;          // 0..4095
        int r = flat >> 5;                 // 0..127
        int c = flat & 31;                 // 16B chunk
        CP16(sdst + r * RSB + c * 16, src + (size_t)r * DIM + c * 8);
    }
}

template <bool DIAG>
__device__ __forceinline__ void fold_tile(const float c_[2][8][4], int colb,
                                          const int rowg[4],
                                          float best[4], int bidx[4]) {
    #pragma unroll
    for (int mi = 0; mi < 2; mi++)
        #pragma unroll
        for (int h = 0; h < 2; h++) {
            const int bi = mi * 2 + h;
            #pragma unroll
            for (int ni = 0; ni < 8; ni++)
                #pragma unroll
                for (int bb = 0; bb < 2; bb++) {
                    float v = c_[mi][ni][h * 2 + bb];
                    int col = colb + ni * 8 + bb;
                    if (DIAG && col == rowg[bi]) continue;
                    if (v > best[bi]) { best[bi] = v; bidx[bi] = col; }
                }
        }
}

// ---------------------------------------------------------------------------
// Kernel 3: fp16 mma.sync GEMM (X @ X^T) with fused per-row argmax.
// grid (64, 16), 256 threads, 198 KB smem: A resident + double-buffered B.
__global__ void __launch_bounds__(256, 1) koleo_gemm() {
    extern __shared__ __align__(16) char smem[];
    const int tid = threadIdx.x;
    const int l   = tid & 31;
    const int wid = tid >> 5;
    const int wm  = wid >> 1;              // 0..3 (M)
    const int wn  = wid & 1;               // 0..1 (N)
    const int rowbase = blockIdx.x * 128;
    const int colg    = blockIdx.y * (TPG * 128);

    const uint32_t suA = smem_u32(smem);
    const uint32_t suB0 = suA + ATILE;

    load_tile_async(suA,  g_xh + (size_t)rowbase * DIM, tid);
    load_tile_async(suB0, g_xh + (size_t)colg * DIM, tid);
    CPCOMMIT();

    // ldmatrix lane-address offsets (bytes)
    const uint32_t aoff = (uint32_t)((wm * 32 + (l & 15)) * RSB + (l >> 4) * 16);
    const uint32_t boff = (uint32_t)((wn * 64 + (l & 7) + ((l >> 4) << 3)) * RSB +
                                     ((l >> 3) & 1) * 16);

    float best[4] = {-2.0f, -2.0f, -2.0f, -2.0f};
    int   bidx[4] = {0, 0, 0, 0};
    int   rowg[4];
    #pragma unroll
    for (int mi = 0; mi < 2; mi++)
        #pragma unroll
        for (int h = 0; h < 2; h++)
            rowg[mi * 2 + h] = rowbase + wm * 32 + mi * 16 + (l >> 2) + h * 8;

    #pragma unroll 1
    for (int t = 0; t < TPG; t++) {
        if (t + 1 < TPG) {
            load_tile_async(suB0 + ((t + 1) & 1) * ATILE,
                            g_xh + (size_t)(colg + (t + 1) * 128) * DIM, tid);
            CPCOMMIT();
            CPWAIT(1);
        } else {
            CPWAIT(0);
        }
        __syncthreads();

        const uint32_t uB = suB0 + (t & 1) * ATILE;
        float c_[2][8][4];
        #pragma unroll
        for (int mi = 0; mi < 2; mi++)
            #pragma unroll
            for (int ni = 0; ni < 8; ni++)
                #pragma unroll
                for (int q = 0; q < 4; q++) c_[mi][ni][q] = 0.0f;

        #pragma unroll
        for (int k = 0; k < 16; k++) {
            uint32_t a0[4], a1[4];
            ldsm4(a0, suA + aoff + k * 32);
            ldsm4(a1, suA + aoff + 16 * RSB + k * 32);
            uint32_t b[4][4];
            #pragma unroll
            for (int p = 0; p < 4; p++)
                ldsm4(b[p], uB + boff + p * 16 * RSB + k * 32);
            #pragma unroll
            for (int ni = 0; ni < 8; ni++) {
                uint32_t b0 = b[ni >> 1][(ni & 1) * 2];
                uint32_t b1 = b[ni >> 1][(ni & 1) * 2 + 1];
                mma16816(c_[0][ni], a0, b0, b1);
                mma16816(c_[1][ni], a1, b0, b1);
            }
        }

        const int colb = colg + t * 128 + wn * 64 + (l & 3) * 2;
        if (colg + t * 128 == rowbase)
            fold_tile<true>(c_, colb, rowg, best, bidx);
        else
            fold_tile<false>(c_, colb, rowg, best, bidx);
        __syncthreads();
    }

    // quad reduce (lanes sharing the same 4 rows differ only in l&3) + atomic
    #pragma unroll
    for (int bi = 0; bi < 4; bi++) {
        unsigned long long p = pack_vi(best[bi], bidx[bi]);
        unsigned long long q = __shfl_xor_sync(0xffffffffu, p, 1);
        if (q > p) p = q;
        q = __shfl_xor_sync(0xffffffffu, p, 2);
        if (q > p) p = q;
        if ((l & 3) == 0) atomicMax(&g_best[rowg[bi]], p);
    }
}

// ---------------------------------------------------------------------------
// Kernel 4: per-row distance + log (exact fp32). One warp per row.
__global__ void koleo_dist() {
    int row  = blockIdx.x * 8 + (threadIdx.x >> 5);
    int lane = threadIdx.x & 31;
    int nb   = unpack_idx(g_best[row]);
    const float4* xi = (const float4*)(g_xn + (size_t)row * DIM);
    const float4* xj = (const float4*)(g_xn + (size_t)nb  * DIM);
    float s = 0.0f;
    #pragma unroll
    for (int c = 0; c < 2; c++) {
        float4 a = xi[lane + c * 32];
        float4 b = xj[lane + c * 32];
        float d0 = a.x - b.x + kEPS, d1 = a.y - b.y + kEPS;
        float d2 = a.z - b.z + kEPS, d3 = a.w - b.w + kEPS;
        s = fmaf(d0, d0, s); s = fmaf(d1, d1, s);
        s = fmaf(d2, d2, s); s = fmaf(d3, d3, s);
    }
    #pragma unroll
    for (int o = 16; o > 0; o >>= 1) s += __shfl_xor_sync(0xffffffffu, s, o);
    if (lane == 0) g_logd[row] = logf(sqrtf(s) + kEPS);
}

// Kernel 5: deterministic reduction -> scalar loss
__global__ void koleo_reduce(float* __restrict__ out) {
    __shared__ float sh[32];
    int tid = threadIdx.x;
    float s = 0.0f;
    #pragma unroll
    for (int i = tid; i < BROWS; i += 1024) s += g_logd[i];
    #pragma unroll
    for (int o = 16; o > 0; o >>= 1) s += __shfl_xor_sync(0xffffffffu, s, o);
    if ((tid & 31) == 0) sh[tid >> 5] = s;
    __syncthreads();
    if (tid < 32) {
        float v = sh[tid];
        #pragma unroll
        for (int o = 16; o > 0; o >>= 1) v += __shfl_xor_sync(0xffffffffu, v, o);
        if (tid == 0) out[0] = -v / (float)BROWS;
    }
}

// ---------------------------------------------------------------------------
extern "C" void kernel_launch(void* const* d_in, const int* in_sizes, int n_in,
                              void* d_out, int out_size) {
    const float* student = (const float*)d_in[0];
    float* out = (float*)d_out;
    (void)in_sizes; (void)n_in; (void)out_size;

    const int smem_bytes = 3 * ATILE;      // 202752 B
    cudaFuncSetAttribute(koleo_gemm, cudaFuncAttributeMaxDynamicSharedMemorySize, smem_bytes);

    koleo_normcvt<<<BROWS, 64>>>(student);
    koleo_init_best<<<(BROWS + 255) / 256, 256>>>();
    koleo_gemm<<<dim3(NRB, NCG), 256, smem_bytes>>>();
    koleo_dist<<<BROWS / 8, 256>>>();
    koleo_reduce<<<1, 1024>>>(out);
}

// round 4
// speedup vs baseline: 9.8472x; 1.3127x over previous
#include <cuda_runtime.h>
#include <cuda_fp16.h>
#include <math.h>
#include <stdint.h>

#define BROWS 8192
#define DIM   256
#define RSB   528           // smem row stride bytes (256 halves + 8 pad)
#define ATILE (128 * RSB)   // 67584 B per tile buffer
#define NCTA  544           // upper-triangle (rowblock, colgroup-of-4) pairs

static __device__ __constant__ float kEPS = 1e-8f;

// ------------------------- device scratch ----------------------------------
__device__ __align__(16) float  g_xn[BROWS * DIM];   // normalized fp32 (8 MB)
__device__ __align__(16) __half g_xh[BROWS * DIM];   // normalized fp16 (4 MB)
__device__ unsigned long long   g_best[BROWS];
__device__ float                g_logd[BROWS];

// ------------------------- helpers -----------------------------------------
__device__ __forceinline__ uint32_t smem_u32(const void* p) {
    uint32_t a;
    asm("{ .reg .u64 t; cvta.to.shared.u64 t, %1; cvt.u32.u64 %0, t; }" : "=r"(a) : "l"(p));
    return a;
}
__device__ __forceinline__ void ldsm4(uint32_t r[4], uint32_t a) {
    asm volatile("ldmatrix.sync.aligned.m8n8.x4.shared.b16 {%0,%1,%2,%3}, [%4];"
                 : "=r"(r[0]), "=r"(r[1]), "=r"(r[2]), "=r"(r[3]) : "r"(a));
}
__device__ __forceinline__ void mma16816(float c[4], const uint32_t a[4],
                                         uint32_t b0, uint32_t b1) {
    asm volatile("mma.sync.aligned.m16n8k16.row.col.f32.f16.f16.f32 "
                 "{%0,%1,%2,%3}, {%4,%5,%6,%7}, {%8,%9}, {%0,%1,%2,%3};"
                 : "+f"(c[0]), "+f"(c[1]), "+f"(c[2]), "+f"(c[3])
                 : "r"(a[0]), "r"(a[1]), "r"(a[2]), "r"(a[3]), "r"(b0), "r"(b1));
}
#define CP16(dst, src)  asm volatile("cp.async.cg.shared.global [%0], [%1], 16;" :: "r"(dst), "l"(src) : "memory")
#define CPCOMMIT()      asm volatile("cp.async.commit_group;" ::: "memory")
#define CPWAIT(n)       asm volatile("cp.async.wait_group %0;" :: "n"(n) : "memory")

// pack: high 32 = orderable key (dot+2 > 0 so raw bits are monotone),
// low 32 = 8191-idx (tie -> smaller index wins under u64 max).
__device__ __forceinline__ unsigned long long pack_vi(float v, int idx) {
    return ((unsigned long long)__float_as_uint(v + 2.0f) << 32) |
           (unsigned)(8191 - idx);
}
__device__ __forceinline__ int unpack_idx(unsigned long long p) {
    return 8191 - (int)(p & 0xFFFFFFFFull);
}
__device__ __forceinline__ unsigned long long u64max(unsigned long long a,
                                                     unsigned long long b) {
    return a > b ? a : b;
}
__device__ __forceinline__ unsigned long long shfl_xor_u64(unsigned long long v, int m) {
    uint32_t lo = (uint32_t)v, hi = (uint32_t)(v >> 32);
    lo = __shfl_xor_sync(0xffffffffu, lo, m);
    hi = __shfl_xor_sync(0xffffffffu, hi, m);
    return ((unsigned long long)hi << 32) | lo;
}

// blockIdx -> (rowblock i, colgroup g); full 4-tile CTAs first (i <= 4g),
// then boundary CTAs (i = 4g+1..4g+3, t0 = i-4g).
__device__ __forceinline__ void map_cta(int b, int& i, int& g) {
    if (b < 496) {
        int gg = 0, rem = b;
        #pragma unroll 1
        for (;;) { int c = 4 * gg + 1; if (rem < c) break; rem -= c; gg++; }
        g = gg; i = rem;
    } else {
        int b2 = b - 496;
        g = b2 / 3;
        i = 4 * g + 1 + (b2 % 3);
    }
}

// ---------------------------------------------------------------------------
// Kernel 1: normalize rows -> fp32 + fp16; also zero g_best. 64 threads/row.
__global__ void koleo_normcvt(const float* __restrict__ x) {
    int row  = blockIdx.x;
    int lane = threadIdx.x;                 // 0..63
    float4 v = ((const float4*)(x + (size_t)row * DIM))[lane];
    float s = v.x * v.x + v.y * v.y + v.z * v.z + v.w * v.w;
    #pragma unroll
    for (int o = 16; o > 0; o >>= 1) s += __shfl_xor_sync(0xffffffffu, s, o);
    __shared__ float sh[2];
    if ((lane & 31) == 0) sh[lane >> 5] = s;
    __syncthreads();
    float inv = 1.0f / fmaxf(sqrtf(sh[0] + sh[1]), kEPS);
    v.x *= inv; v.y *= inv; v.z *= inv; v.w *= inv;
    ((float4*)(g_xn + (size_t)row * DIM))[lane] = v;

    ushort4 H;
    H.x = __half_as_ushort(__float2half_rn(v.x));
    H.y = __half_as_ushort(__float2half_rn(v.y));
    H.z = __half_as_ushort(__float2half_rn(v.z));
    H.w = __half_as_ushort(__float2half_rn(v.w));
    *(ushort4*)(g_xh + (size_t)row * DIM + lane * 4) = H;
    if (lane == 0) g_best[row] = 0ull;
}

// ---------------------------------------------------------------------------
__device__ __forceinline__ void load_tile_async(uint32_t sdst,
                                                const __half* __restrict__ src,
                                                int tid) {
    #pragma unroll
    for (int i = 0; i < 16; i++) {
        int flat = tid + i * 256;
        int r = flat >> 5;
        int c = flat & 31;
        CP16(sdst + r * RSB + c * 16, src + (size_t)r * DIM + c * 8);
    }
}

template <bool DIAG>
__device__ __forceinline__ void fold_rows(const float c_[2][8][4], int colb,
                                          const int rowg[4],
                                          float best[4], int bidx[4]) {
    #pragma unroll
    for (int mi = 0; mi < 2; mi++)
        #pragma unroll
        for (int h = 0; h < 2; h++) {
            const int bi = mi * 2 + h;
            #pragma unroll
            for (int ni = 0; ni < 8; ni++)
                #pragma unroll
                for (int bb = 0; bb < 2; bb++) {
                    float v = c_[mi][ni][h * 2 + bb];
                    int col = colb + ni * 8 + bb;
                    if (DIAG && col == rowg[bi]) continue;
                    if (v > best[bi]) { best[bi] = v; bidx[bi] = col; }
                }
        }
}

// ---------------------------------------------------------------------------
// Kernel 2: fp16 mma.sync X@X^T, upper-triangular tiles only, dual fold.
// 544 CTAs, 256 threads, 198 KB dyn smem (A resident + double-buffered B).
__global__ void __launch_bounds__(256, 1) koleo_gemm() {
    extern __shared__ __align__(16) char smem[];
    __shared__ unsigned long long scol[128][4];

    const int tid = threadIdx.x;
    const int l   = tid & 31;
    const int wid = tid >> 5;
    const int wm  = wid >> 1;
    const int wn  = wid & 1;

    int ib, gb;
    map_cta(blockIdx.x, ib, gb);
    const int rowbase = ib * 128;
    const int colg    = gb * 512;
    const int t0      = (ib - 4 * gb > 0) ? (ib - 4 * gb) : 0;

    const uint32_t suA  = smem_u32(smem);
    const uint32_t suB0 = suA + ATILE;

    load_tile_async(suA,  g_xh + (size_t)rowbase * DIM, tid);
    load_tile_async(suB0 + (t0 & 1) * ATILE, g_xh + (size_t)(colg + t0 * 128) * DIM, tid);
    CPCOMMIT();

    const uint32_t aoff = (uint32_t)((wm * 32 + (l & 15)) * RSB + (l >> 4) * 16);
    const uint32_t boff = (uint32_t)((wn * 64 + (l & 7) + ((l >> 4) << 3)) * RSB +
                                     ((l >> 3) & 1) * 16);

    float best[4] = {-2.0f, -2.0f, -2.0f, -2.0f};
    int   bidx[4] = {0, 0, 0, 0};
    int   rowg[4];
    const int rloc = wm * 32 + (l >> 2);       // mi=0,h=0 local row
    #pragma unroll
    for (int mi = 0; mi < 2; mi++)
        #pragma unroll
        for (int h = 0; h < 2; h++)
            rowg[mi * 2 + h] = rowbase + rloc + mi * 16 + h * 8;

    #pragma unroll 1
    for (int t = t0; t < 4; t++) {
        if (t + 1 < 4) {
            load_tile_async(suB0 + ((t + 1) & 1) * ATILE,
                            g_xh + (size_t)(colg + (t + 1) * 128) * DIM, tid);
            CPCOMMIT();
            CPWAIT(1);
        } else {
            CPWAIT(0);
        }
        __syncthreads();

        const uint32_t uB = suB0 + (t & 1) * ATILE;
        float c_[2][8][4];
        #pragma unroll
        for (int mi = 0; mi < 2; mi++)
            #pragma unroll
            for (int ni = 0; ni < 8; ni++)
                #pragma unroll
                for (int q = 0; q < 4; q++) c_[mi][ni][q] = 0.0f;

        #pragma unroll
        for (int k = 0; k < 16; k++) {
            uint32_t a0[4], a1[4];
            ldsm4(a0, suA + aoff + k * 32);
            ldsm4(a1, suA + aoff + 16 * RSB + k * 32);
            uint32_t b[4][4];
            #pragma unroll
            for (int p = 0; p < 4; p++)
                ldsm4(b[p], uB + boff + p * 16 * RSB + k * 32);
            #pragma unroll
            for (int ni = 0; ni < 8; ni++) {
                uint32_t b0 = b[ni >> 1][(ni & 1) * 2];
                uint32_t b1 = b[ni >> 1][(ni & 1) * 2 + 1];
                mma16816(c_[0][ni], a0, b0, b1);
                mma16816(c_[1][ni], a1, b0, b1);
            }
        }

        const int tilecol = colg + t * 128;
        const bool diag = (tilecol == rowbase);
        const int colb = tilecol + wn * 64 + (l & 3) * 2;

        if (diag) fold_rows<true >(c_, colb, rowg, best, bidx);
        else      fold_rows<false>(c_, colb, rowg, best, bidx);

        if (!diag) {
            // column fold: per (ni,bb) reduce over mi/h, then over lane
            // groups (xor 4/8/16), per-warp result -> scol[col][wm].
            #pragma unroll
            for (int ni = 0; ni < 8; ni++)
                #pragma unroll
                for (int bb = 0; bb < 2; bb++) {
                    float bv = c_[0][ni][bb];      int br = rloc;
                    float v;
                    v = c_[0][ni][2 + bb]; if (v > bv) { bv = v; br = rloc + 8;  }
                    v = c_[1][ni][bb];     if (v > bv) { bv = v; br = rloc + 16; }
                    v = c_[1][ni][2 + bb]; if (v > bv) { bv = v; br = rloc + 24; }
                    unsigned long long p = pack_vi(bv, rowbase + br);
                    p = u64max(p, shfl_xor_u64(p, 4));
                    p = u64max(p, shfl_xor_u64(p, 8));
                    p = u64max(p, shfl_xor_u64(p, 16));
                    if ((l >> 2) == 0)
                        scol[wn * 64 + ni * 8 + (l & 3) * 2 + bb][wm] = p;
                }
            __syncthreads();
            if (tid < 128) {
                unsigned long long m = u64max(u64max(scol[tid][0], scol[tid][1]),
                                              u64max(scol[tid][2], scol[tid][3]));
                atomicMax(&g_best[tilecol + tid], m);
            }
        }
        __syncthreads();
    }

    // row-side quad reduce + atomic
    #pragma unroll
    for (int bi = 0; bi < 4; bi++) {
        unsigned long long p = pack_vi(best[bi], bidx[bi]);
        p = u64max(p, shfl_xor_u64(p, 1));
        p = u64max(p, shfl_xor_u64(p, 2));
        if ((l & 3) == 0) atomicMax(&g_best[rowg[bi]], p);
    }
}

// ---------------------------------------------------------------------------
// Kernel 3: per-row distance + log (exact fp32). One warp per row.
__global__ void koleo_dist() {
    int row  = blockIdx.x * 8 + (threadIdx.x >> 5);
    int lane = threadIdx.x & 31;
    int nb   = unpack_idx(g_best[row]);
    const float4* xi = (const float4*)(g_xn + (size_t)row * DIM);
    const float4* xj = (const float4*)(g_xn + (size_t)nb  * DIM);
    float s = 0.0f;
    #pragma unroll
    for (int c = 0; c < 2; c++) {
        float4 a = xi[lane + c * 32];
        float4 b = xj[lane + c * 32];
        float d0 = a.x - b.x + kEPS, d1 = a.y - b.y + kEPS;
        float d2 = a.z - b.z + kEPS, d3 = a.w - b.w + kEPS;
        s = fmaf(d0, d0, s); s = fmaf(d1, d1, s);
        s = fmaf(d2, d2, s); s = fmaf(d3, d3, s);
    }
    #pragma unroll
    for (int o = 16; o > 0; o >>= 1) s += __shfl_xor_sync(0xffffffffu, s, o);
    if (lane == 0) g_logd[row] = logf(sqrtf(s) + kEPS);
}

// Kernel 4: deterministic reduction -> scalar loss
__global__ void koleo_reduce(float* __restrict__ out) {
    __shared__ float sh[32];
    int tid = threadIdx.x;
    float s = 0.0f;
    #pragma unroll
    for (int i = tid; i < BROWS; i += 1024) s += g_logd[i];
    #pragma unroll
    for (int o = 16; o > 0; o >>= 1) s += __shfl_xor_sync(0xffffffffu, s, o);
    if ((tid & 31) == 0) sh[tid >> 5] = s;
    __syncthreads();
    if (tid < 32) {
        float v = sh[tid];
        #pragma unroll
        for (int o = 16; o > 0; o >>= 1) v += __shfl_xor_sync(0xffffffffu, v, o);
        if (tid == 0) out[0] = -v / (float)BROWS;
    }
}

// ---------------------------------------------------------------------------
extern "C" void kernel_launch(void* const* d_in, const int* in_sizes, int n_in,
                              void* d_out, int out_size) {
    const float* student = (const float*)d_in[0];
    float* out = (float*)d_out;
    (void)in_sizes; (void)n_in; (void)out_size;

    const int smem_bytes = 3 * ATILE;      // 202752 B dynamic
    cudaFuncSetAttribute(koleo_gemm, cudaFuncAttributeMaxDynamicSharedMemorySize, smem_bytes);

    koleo_normcvt<<<BROWS, 64>>>(student);
    koleo_gemm<<<NCTA, 256, smem_bytes>>>();
    koleo_dist<<<BROWS / 8, 256>>>();
    koleo_reduce<<<1, 1024>>>(out);
}

// round 5
// speedup vs baseline: 10.7232x; 1.0890x over previous
#include <cuda_runtime.h>
#include <cuda_fp16.h>
#include <math.h>
#include <stdint.h>

#define BROWS 8192
#define DIM   256
#define RSB   528           // smem row stride bytes (256 halves + 8 pad)
#define ATILE (128 * RSB)   // 67584 B per tile slot (1024-aligned multiple)
#define NCTA  148

static __device__ __constant__ float kEPS = 1e-8f;

// ------------------------- device scratch ----------------------------------
__device__ __align__(16) float  g_xn[BROWS * DIM];   // normalized fp32 (8 MB)
__device__ __align__(16) __half g_xh[BROWS * DIM];   // normalized fp16 (4 MB)
__device__ unsigned long long   g_best[BROWS];

// ------------------------- helpers -----------------------------------------
__device__ __forceinline__ uint32_t smem_u32(const void* p) {
    uint32_t a;
    asm("{ .reg .u64 t; cvta.to.shared.u64 t, %1; cvt.u32.u64 %0, t; }" : "=r"(a) : "l"(p));
    return a;
}
__device__ __forceinline__ void ldsm4(uint32_t r[4], uint32_t a) {
    asm volatile("ldmatrix.sync.aligned.m8n8.x4.shared.b16 {%0,%1,%2,%3}, [%4];"
                 : "=r"(r[0]), "=r"(r[1]), "=r"(r[2]), "=r"(r[3]) : "r"(a));
}
__device__ __forceinline__ void mma16816(float c[4], const uint32_t a[4],
                                         uint32_t b0, uint32_t b1) {
    asm volatile("mma.sync.aligned.m16n8k16.row.col.f32.f16.f16.f32 "
                 "{%0,%1,%2,%3}, {%4,%5,%6,%7}, {%8,%9}, {%0,%1,%2,%3};"
                 : "+f"(c[0]), "+f"(c[1]), "+f"(c[2]), "+f"(c[3])
                 : "r"(a[0]), "r"(a[1]), "r"(a[2]), "r"(a[3]), "r"(b0), "r"(b1));
}
#define CP16(dst, src)  asm volatile("cp.async.cg.shared.global [%0], [%1], 16;" :: "r"(dst), "l"(src) : "memory")
#define CPCOMMIT()      asm volatile("cp.async.commit_group;" ::: "memory")
#define CPWAIT0()       asm volatile("cp.async.wait_group 0;" ::: "memory")

// pack: high 32 = orderable key (dot+2 > 0), low 32 = 8191-idx (tie -> smaller idx)
__device__ __forceinline__ unsigned long long pack_vi(float v, int idx) {
    return ((unsigned long long)__float_as_uint(v + 2.0f) << 32) |
           (unsigned)(8191 - idx);
}
__device__ __forceinline__ int unpack_idx(unsigned long long p) {
    return 8191 - (int)(p & 0xFFFFFFFFull);
}
__device__ __forceinline__ unsigned long long u64max(unsigned long long a,
                                                     unsigned long long b) {
    return a > b ? a : b;
}
__device__ __forceinline__ unsigned long long shfl_xor_u64(unsigned long long v, int m) {
    uint32_t lo = (uint32_t)v, hi = (uint32_t)(v >> 32);
    lo = __shfl_xor_sync(0xffffffffu, lo, m);
    hi = __shfl_xor_sync(0xffffffffu, hi, m);
    return ((unsigned long long)hi << 32) | lo;
}

// ---------------------------------------------------------------------------
// Kernel 1: normalize rows -> fp32 + fp16; zero g_best; zero out. 1 warp/row.
__global__ void koleo_normcvt(const float* __restrict__ x, float* __restrict__ out) {
    int row  = blockIdx.x * 8 + (threadIdx.x >> 5);
    int lane = threadIdx.x & 31;
    const float4* src = (const float4*)(x + (size_t)row * DIM);
    float4 v0 = src[lane];
    float4 v1 = src[lane + 32];
    float s = v0.x*v0.x + v0.y*v0.y + v0.z*v0.z + v0.w*v0.w
            + v1.x*v1.x + v1.y*v1.y + v1.z*v1.z + v1.w*v1.w;
    #pragma unroll
    for (int o = 16; o > 0; o >>= 1) s += __shfl_xor_sync(0xffffffffu, s, o);
    float inv = 1.0f / fmaxf(sqrtf(s), kEPS);
    v0.x *= inv; v0.y *= inv; v0.z *= inv; v0.w *= inv;
    v1.x *= inv; v1.y *= inv; v1.z *= inv; v1.w *= inv;
    float4* dst = (float4*)(g_xn + (size_t)row * DIM);
    dst[lane] = v0; dst[lane + 32] = v1;

    ushort4 H0, H1;
    H0.x = __half_as_ushort(__float2half_rn(v0.x));
    H0.y = __half_as_ushort(__float2half_rn(v0.y));
    H0.z = __half_as_ushort(__float2half_rn(v0.z));
    H0.w = __half_as_ushort(__float2half_rn(v0.w));
    H1.x = __half_as_ushort(__float2half_rn(v1.x));
    H1.y = __half_as_ushort(__float2half_rn(v1.y));
    H1.z = __half_as_ushort(__float2half_rn(v1.z));
    H1.w = __half_as_ushort(__float2half_rn(v1.w));
    ushort4* hdst = (ushort4*)(g_xh + (size_t)row * DIM);
    hdst[lane] = H0; hdst[lane + 32] = H1;
    if (lane == 0) g_best[row] = 0ull;
    if (blockIdx.x == 0 && threadIdx.x == 0) out[0] = 0.0f;
}

// ---------------------------------------------------------------------------
__device__ __forceinline__ void load_tile_async(uint32_t sdst,
                                                const __half* __restrict__ src,
                                                int tid) {
    #pragma unroll
    for (int i = 0; i < 16; i++) {
        int flat = tid + i * 256;
        int r = flat >> 5;
        int c = flat & 31;
        CP16(sdst + r * RSB + c * 16, src + (size_t)r * DIM + c * 8);
    }
}

__device__ __forceinline__ void mma_tile(float (&c_)[2][8][4], uint32_t uA, uint32_t uB,
                                         uint32_t aoff, uint32_t boff) {
    #pragma unroll
    for (int mi = 0; mi < 2; mi++)
        #pragma unroll
        for (int ni = 0; ni < 8; ni++)
            #pragma unroll
            for (int q = 0; q < 4; q++) c_[mi][ni][q] = 0.0f;
    #pragma unroll
    for (int k = 0; k < 16; k++) {
        uint32_t a0[4], a1[4];
        ldsm4(a0, uA + aoff + k * 32);
        ldsm4(a1, uA + aoff + 16 * RSB + k * 32);
        uint32_t b[4][4];
        #pragma unroll
        for (int p = 0; p < 4; p++)
            ldsm4(b[p], uB + boff + p * 16 * RSB + k * 32);
        #pragma unroll
        for (int ni = 0; ni < 8; ni++) {
            uint32_t b0 = b[ni >> 1][(ni & 1) * 2];
            uint32_t b1 = b[ni >> 1][(ni & 1) * 2 + 1];
            mma16816(c_[0][ni], a0, b0, b1);
            mma16816(c_[1][ni], a1, b0, b1);
        }
    }
}

// fold tile (pi, pj): row-side into running best, column-side via REDG.
__device__ __forceinline__ void fold_tile(const float (&c_)[2][8][4], int pi, int pj,
                                          int rloc, int wn, int l,
                                          float best[4], int bidx[4]) {
    const int colb = pj * 128 + wn * 64 + (l & 3) * 2;
    const int rbase = pi * 128 + rloc;
    if (pi == pj) {
        #pragma unroll
        for (int mi = 0; mi < 2; mi++)
            #pragma unroll
            for (int h = 0; h < 2; h++) {
                const int bi = mi * 2 + h;
                const int row = rbase + mi * 16 + h * 8;
                #pragma unroll
                for (int ni = 0; ni < 8; ni++)
                    #pragma unroll
                    for (int bb = 0; bb < 2; bb++) {
                        float v = c_[mi][ni][h * 2 + bb];
                        int col = colb + ni * 8 + bb;
                        if (col == row) continue;
                        if (v > best[bi]) { best[bi] = v; bidx[bi] = col; }
                    }
            }
    } else {
        #pragma unroll
        for (int mi = 0; mi < 2; mi++)
            #pragma unroll
            for (int h = 0; h < 2; h++) {
                const int bi = mi * 2 + h;
                #pragma unroll
                for (int ni = 0; ni < 8; ni++)
                    #pragma unroll
                    for (int bb = 0; bb < 2; bb++) {
                        float v = c_[mi][ni][h * 2 + bb];
                        int col = colb + ni * 8 + bb;
                        if (v > best[bi]) { best[bi] = v; bidx[bi] = col; }
                    }
            }
        // column fold: per (ni,bb), max over (mi,h) then lanes xor 4/8/16; REDG.
        #pragma unroll
        for (int ni = 0; ni < 8; ni++)
            #pragma unroll
            for (int bb = 0; bb < 2; bb++) {
                float bv = c_[0][ni][bb];      int br = rbase;
                float v;
                v = c_[0][ni][2 + bb]; if (v > bv) { bv = v; br = rbase + 8;  }
                v = c_[1][ni][bb];     if (v > bv) { bv = v; br = rbase + 16; }
                v = c_[1][ni][2 + bb]; if (v > bv) { bv = v; br = rbase + 24; }
                unsigned long long p = pack_vi(bv, br);
                p = u64max(p, shfl_xor_u64(p, 4));
                p = u64max(p, shfl_xor_u64(p, 8));
                p = u64max(p, shfl_xor_u64(p, 16));
                if ((l >> 2) == 0)
                    atomicMax(&g_best[colb + ni * 8 + bb], p);
            }
    }
}

__device__ __forceinline__ void flush_rows(int rowblk, int rloc, int l,
                                           float best[4], int bidx[4]) {
    #pragma unroll
    for (int bi = 0; bi < 4; bi++) {
        unsigned long long p = pack_vi(best[bi], bidx[bi]);
        p = u64max(p, shfl_xor_u64(p, 1));
        p = u64max(p, shfl_xor_u64(p, 2));
        if ((l & 3) == 0) {
            int row = rowblk * 128 + rloc + (bi >> 1) * 16 + (bi & 1) * 8;
            atomicMax(&g_best[row], p);
        }
        best[bi] = -2.0f; bidx[bi] = 0;
    }
}

__device__ __forceinline__ int free_slot(int sa, int sb) {
    if (sa != 0 && sb != 0) return 0;
    if (sa != 1 && sb != 1) return 1;
    return 2;
}

// ---------------------------------------------------------------------------
// Kernel 2: persistent balanced upper-tri GEMM-argmax. 148 CTAs, 256 thr.
__global__ void __launch_bounds__(256, 1) koleo_gemm() {
    extern __shared__ __align__(16) char smem[];
    const uint32_t su = smem_u32(smem);
    const int tid = threadIdx.x;
    const int l   = tid & 31;
    const int wid = tid >> 5;
    const int wm  = wid >> 1;
    const int wn  = wid & 1;
    const int rloc = wm * 32 + (l >> 2);
    const int b   = blockIdx.x;

    const int cnt = 14 + (b < 8 ? 1 : 0);
    int s = b * 14 + (b < 8 ? b : 8);
    int i = 0;
    while (s >= 64 - i) { s -= 64 - i; i++; }
    int j = i + s;

    const uint32_t aoff = (uint32_t)((wm * 32 + (l & 15)) * RSB + (l >> 4) * 16);
    const uint32_t boff = (uint32_t)((wn * 64 + (l & 7) + ((l >> 4) << 3)) * RSB +
                                     ((l >> 3) & 1) * 16);

    // initial loads
    int sa = 0, sb;
    load_tile_async(su, g_xh + (size_t)i * 128 * DIM, tid);
    if (j != i) {
        load_tile_async(su + ATILE, g_xh + (size_t)j * 128 * DIM, tid);
        sb = 1;
    } else sb = 0;
    CPCOMMIT();

    float best[4] = {-2.0f, -2.0f, -2.0f, -2.0f};
    int   bidx[4] = {0, 0, 0, 0};
    float c0[2][8][4], c1[2][8][4];
    int pi = -1, pj = -1;

    #pragma unroll 1
    for (int n = 0; n < cnt; n++) {
        CPWAIT0();
        __syncthreads();

        int nsa = sa, nsb = sb, ii2 = i, jj2 = j;
        if (n + 1 < cnt) {
            int fs = free_slot(sa, sb);
            if (j + 1 < 64) {
                load_tile_async(su + fs * ATILE, g_xh + (size_t)(j + 1) * 128 * DIM, tid);
                nsb = fs; jj2 = j + 1;
            } else {
                load_tile_async(su + fs * ATILE, g_xh + (size_t)(i + 1) * 128 * DIM, tid);
                nsa = fs; nsb = fs; ii2 = i + 1; jj2 = i + 1;
            }
            CPCOMMIT();
        }

        if ((n & 1) == 0) {
            mma_tile(c0, su + sa * ATILE, su + sb * ATILE, aoff, boff);
            if (n > 0) {
                fold_tile(c1, pi, pj, rloc, wn, l, best, bidx);
                if (pi != i) flush_rows(pi, rloc, l, best, bidx);
            }
        } else {
            mma_tile(c1, su + sa * ATILE, su + sb * ATILE, aoff, boff);
            fold_tile(c0, pi, pj, rloc, wn, l, best, bidx);
            if (pi != i) flush_rows(pi, rloc, l, best, bidx);
        }
        pi = i; pj = j;
        sa = nsa; sb = nsb; i = ii2; j = jj2;
    }

    // final fold + flush
    if (((cnt - 1) & 1) == 0) fold_tile(c0, pi, pj, rloc, wn, l, best, bidx);
    else                      fold_tile(c1, pi, pj, rloc, wn, l, best, bidx);
    flush_rows(pi, rloc, l, best, bidx);
}

// ---------------------------------------------------------------------------
// Kernel 3: per-row distance + log + fused reduction. One warp per row.
__global__ void koleo_dist(float* __restrict__ out) {
    __shared__ float sh[8];
    int row  = blockIdx.x * 8 + (threadIdx.x >> 5);
    int lane = threadIdx.x & 31;
    int nb   = unpack_idx(g_best[row]);
    const float4* xi = (const float4*)(g_xn + (size_t)row * DIM);
    const float4* xj = (const float4*)(g_xn + (size_t)nb  * DIM);
    float s = 0.0f;
    #pragma unroll
    for (int c = 0; c < 2; c++) {
        float4 a = xi[lane + c * 32];
        float4 b = xj[lane + c * 32];
        float d0 = a.x - b.x + kEPS, d1 = a.y - b.y + kEPS;
        float d2 = a.z - b.z + kEPS, d3 = a.w - b.w + kEPS;
        s = fmaf(d0, d0, s); s = fmaf(d1, d1, s);
        s = fmaf(d2, d2, s); s = fmaf(d3, d3, s);
    }
    #pragma unroll
    for (int o = 16; o > 0; o >>= 1) s += __shfl_xor_sync(0xffffffffu, s, o);
    if (lane == 0) sh[threadIdx.x >> 5] = logf(sqrtf(s) + kEPS);
    __syncthreads();
    if (threadIdx.x == 0) {
        float t = sh[0] + sh[1] + sh[2] + sh[3] + sh[4] + sh[5] + sh[6] + sh[7];
        atomicAdd(out, t * (-1.0f / (float)BROWS));
    }
}

// ---------------------------------------------------------------------------
extern "C" void kernel_launch(void* const* d_in, const int* in_sizes, int n_in,
                              void* d_out, int out_size) {
    const float* student = (const float*)d_in[0];
    float* out = (float*)d_out;
    (void)in_sizes; (void)n_in; (void)out_size;

    const int smem_bytes = 3 * ATILE;      // 202752 B dynamic
    cudaFuncSetAttribute(koleo_gemm, cudaFuncAttributeMaxDynamicSharedMemorySize, smem_bytes);

    koleo_normcvt<<<BROWS / 8, 256>>>(student, out);
    koleo_gemm<<<NCTA, 256, smem_bytes>>>();
    koleo_dist<<<BROWS / 8, 256>>>(out);
}

// round 6
// speedup vs baseline: 10.8144x; 1.0085x over previous
#include <cuda_runtime.h>
#include <cuda_fp16.h>
#include <math.h>
#include <stdint.h>

#define BROWS 8192
#define DIM   256
#define RSB   528           // smem row stride bytes (256 halves + 8 pad)
#define ATILE (128 * RSB)   // 67584 B per tile slot
#define NCTA  148

static __device__ __constant__ float kEPS = 1e-8f;

// ------------------------- device scratch ----------------------------------
__device__ __align__(16) __half g_xh[BROWS * DIM];   // normalized fp16 (4 MB)
__device__ float                g_inv[BROWS];        // per-row 1/norm
__device__ unsigned long long   g_best[BROWS];

// ------------------------- helpers -----------------------------------------
__device__ __forceinline__ uint32_t smem_u32(const void* p) {
    uint32_t a;
    asm("{ .reg .u64 t; cvta.to.shared.u64 t, %1; cvt.u32.u64 %0, t; }" : "=r"(a) : "l"(p));
    return a;
}
__device__ __forceinline__ void ldsm4(uint32_t r[4], uint32_t a) {
    asm volatile("ldmatrix.sync.aligned.m8n8.x4.shared.b16 {%0,%1,%2,%3}, [%4];"
                 : "=r"(r[0]), "=r"(r[1]), "=r"(r[2]), "=r"(r[3]) : "r"(a));
}
__device__ __forceinline__ void mma16816(float c[4], const uint32_t a[4],
                                         uint32_t b0, uint32_t b1) {
    asm volatile("mma.sync.aligned.m16n8k16.row.col.f32.f16.f16.f32 "
                 "{%0,%1,%2,%3}, {%4,%5,%6,%7}, {%8,%9}, {%0,%1,%2,%3};"
                 : "+f"(c[0]), "+f"(c[1]), "+f"(c[2]), "+f"(c[3])
                 : "r"(a[0]), "r"(a[1]), "r"(a[2]), "r"(a[3]), "r"(b0), "r"(b1));
}
#define CP16(dst, src)  asm volatile("cp.async.cg.shared.global [%0], [%1], 16;" :: "r"(dst), "l"(src) : "memory")
#define CPCOMMIT()      asm volatile("cp.async.commit_group;" ::: "memory")
#define CPWAIT0()       asm volatile("cp.async.wait_group 0;" ::: "memory")

// pack: high 32 = orderable key (dot+2 > 0), low 32 = 8191-idx (tie -> smaller idx)
__device__ __forceinline__ unsigned long long pack_vi(float v, int idx) {
    return ((unsigned long long)__float_as_uint(v + 2.0f) << 32) |
           (unsigned)(8191 - idx);
}
__device__ __forceinline__ int unpack_idx(unsigned long long p) {
    return 8191 - (int)(p & 0xFFFFFFFFull);
}
__device__ __forceinline__ unsigned long long u64max(unsigned long long a,
                                                     unsigned long long b) {
    return a > b ? a : b;
}
__device__ __forceinline__ unsigned long long shfl_xor_u64(unsigned long long v, int m) {
    uint32_t lo = (uint32_t)v, hi = (uint32_t)(v >> 32);
    lo = __shfl_xor_sync(0xffffffffu, lo, m);
    hi = __shfl_xor_sync(0xffffffffu, hi, m);
    return ((unsigned long long)hi << 32) | lo;
}

// ---------------------------------------------------------------------------
// Kernel 1: normalize -> fp16 + inv-norm; zero g_best; zero out. 1 warp/row.
__global__ void koleo_normcvt(const float* __restrict__ x, float* __restrict__ out) {
    int row  = blockIdx.x * 8 + (threadIdx.x >> 5);
    int lane = threadIdx.x & 31;
    const float4* src = (const float4*)(x + (size_t)row * DIM);
    float4 v0 = src[lane];
    float4 v1 = src[lane + 32];
    float s = v0.x*v0.x + v0.y*v0.y + v0.z*v0.z + v0.w*v0.w
            + v1.x*v1.x + v1.y*v1.y + v1.z*v1.z + v1.w*v1.w;
    #pragma unroll
    for (int o = 16; o > 0; o >>= 1) s += __shfl_xor_sync(0xffffffffu, s, o);
    float inv = 1.0f / fmaxf(sqrtf(s), kEPS);
    v0.x *= inv; v0.y *= inv; v0.z *= inv; v0.w *= inv;
    v1.x *= inv; v1.y *= inv; v1.z *= inv; v1.w *= inv;

    ushort4 H0, H1;
    H0.x = __half_as_ushort(__float2half_rn(v0.x));
    H0.y = __half_as_ushort(__float2half_rn(v0.y));
    H0.z = __half_as_ushort(__float2half_rn(v0.z));
    H0.w = __half_as_ushort(__float2half_rn(v0.w));
    H1.x = __half_as_ushort(__float2half_rn(v1.x));
    H1.y = __half_as_ushort(__float2half_rn(v1.y));
    H1.z = __half_as_ushort(__float2half_rn(v1.z));
    H1.w = __half_as_ushort(__float2half_rn(v1.w));
    ushort4* hdst = (ushort4*)(g_xh + (size_t)row * DIM);
    hdst[lane] = H0; hdst[lane + 32] = H1;
    if (lane == 0) { g_inv[row] = inv; g_best[row] = 0ull; }
    if (blockIdx.x == 0 && threadIdx.x == 0) out[0] = 0.0f;
}

// ---------------------------------------------------------------------------
__device__ __forceinline__ void load_tile_async(uint32_t sdst,
                                                const __half* __restrict__ src,
                                                int tid) {
    #pragma unroll
    for (int i = 0; i < 16; i++) {
        int flat = tid + i * 256;
        int r = flat >> 5;
        int c = flat & 31;
        CP16(sdst + r * RSB + c * 16, src + (size_t)r * DIM + c * 8);
    }
}

__device__ __forceinline__ void mma_tile(float (&c_)[2][8][4], uint32_t uA, uint32_t uB,
                                         uint32_t aoff, uint32_t boff) {
    #pragma unroll
    for (int mi = 0; mi < 2; mi++)
        #pragma unroll
        for (int ni = 0; ni < 8; ni++)
            #pragma unroll
            for (int q = 0; q < 4; q++) c_[mi][ni][q] = 0.0f;
    #pragma unroll
    for (int k = 0; k < 16; k++) {
        uint32_t a0[4], a1[4];
        ldsm4(a0, uA + aoff + k * 32);
        ldsm4(a1, uA + aoff + 16 * RSB + k * 32);
        uint32_t b[4][4];
        #pragma unroll
        for (int p = 0; p < 4; p++)
            ldsm4(b[p], uB + boff + p * 16 * RSB + k * 32);
        #pragma unroll
        for (int ni = 0; ni < 8; ni++) {
            uint32_t b0 = b[ni >> 1][(ni & 1) * 2];
            uint32_t b1 = b[ni >> 1][(ni & 1) * 2 + 1];
            mma16816(c_[0][ni], a0, b0, b1);
            mma16816(c_[1][ni], a1, b0, b1);
        }
    }
}

// fold tile (pi, pj): row-side into running best, column-side via REDG.
__device__ __forceinline__ void fold_tile(const float (&c_)[2][8][4], int pi, int pj,
                                          int rloc, int wn, int l,
                                          float best[4], int bidx[4]) {
    const int colb = pj * 128 + wn * 64 + (l & 3) * 2;
    const int rbase = pi * 128 + rloc;
    if (pi == pj) {
        #pragma unroll
        for (int mi = 0; mi < 2; mi++)
            #pragma unroll
            for (int h = 0; h < 2; h++) {
                const int bi = mi * 2 + h;
                const int row = rbase + mi * 16 + h * 8;
                #pragma unroll
                for (int ni = 0; ni < 8; ni++)
                    #pragma unroll
                    for (int bb = 0; bb < 2; bb++) {
                        float v = c_[mi][ni][h * 2 + bb];
                        int col = colb + ni * 8 + bb;
                        if (col == row) continue;
                        if (v > best[bi]) { best[bi] = v; bidx[bi] = col; }
                    }
            }
    } else {
        #pragma unroll
        for (int mi = 0; mi < 2; mi++)
            #pragma unroll
            for (int h = 0; h < 2; h++) {
                const int bi = mi * 2 + h;
                #pragma unroll
                for (int ni = 0; ni < 8; ni++)
                    #pragma unroll
                    for (int bb = 0; bb < 2; bb++) {
                        float v = c_[mi][ni][h * 2 + bb];
                        int col = colb + ni * 8 + bb;
                        if (v > best[bi]) { best[bi] = v; bidx[bi] = col; }
                    }
            }
        // column fold: per (ni,bb), max over (mi,h) then lanes xor 4/8/16; REDG.
        #pragma unroll
        for (int ni = 0; ni < 8; ni++)
            #pragma unroll
            for (int bb = 0; bb < 2; bb++) {
                float bv = c_[0][ni][bb];      int br = rbase;
                float v;
                v = c_[0][ni][2 + bb]; if (v > bv) { bv = v; br = rbase + 8;  }
                v = c_[1][ni][bb];     if (v > bv) { bv = v; br = rbase + 16; }
                v = c_[1][ni][2 + bb]; if (v > bv) { bv = v; br = rbase + 24; }
                unsigned long long p = pack_vi(bv, br);
                p = u64max(p, shfl_xor_u64(p, 4));
                p = u64max(p, shfl_xor_u64(p, 8));
                p = u64max(p, shfl_xor_u64(p, 16));
                if ((l >> 2) == 0)
                    atomicMax(&g_best[colb + ni * 8 + bb], p);
            }
    }
}

__device__ __forceinline__ void flush_rows(int rowblk, int rloc, int l,
                                           float best[4], int bidx[4]) {
    #pragma unroll
    for (int bi = 0; bi < 4; bi++) {
        unsigned long long p = pack_vi(best[bi], bidx[bi]);
        p = u64max(p, shfl_xor_u64(p, 1));
        p = u64max(p, shfl_xor_u64(p, 2));
        if ((l & 3) == 0) {
            int row = rowblk * 128 + rloc + (bi >> 1) * 16 + (bi & 1) * 8;
            atomicMax(&g_best[row], p);
        }
        best[bi] = -2.0f; bidx[bi] = 0;
    }
}

__device__ __forceinline__ int free_slot(int sa, int sb) {
    if (sa != 0 && sb != 0) return 0;
    if (sa != 1 && sb != 1) return 1;
    return 2;
}

// ---------------------------------------------------------------------------
// Kernel 2: persistent balanced upper-tri GEMM-argmax. 148 CTAs, 256 thr.
__global__ void __launch_bounds__(256, 1) koleo_gemm() {
    extern __shared__ __align__(16) char smem[];
    const uint32_t su = smem_u32(smem);
    const int tid = threadIdx.x;
    const int l   = tid & 31;
    const int wid = tid >> 5;
    const int wm  = wid >> 1;
    const int wn  = wid & 1;
    const int rloc = wm * 32 + (l >> 2);
    const int b   = blockIdx.x;

    const int cnt = 14 + (b < 8 ? 1 : 0);
    int s = b * 14 + (b < 8 ? b : 8);
    int i = 0;
    while (s >= 64 - i) { s -= 64 - i; i++; }
    int j = i + s;

    const uint32_t aoff = (uint32_t)((wm * 32 + (l & 15)) * RSB + (l >> 4) * 16);
    const uint32_t boff = (uint32_t)((wn * 64 + (l & 7) + ((l >> 4) << 3)) * RSB +
                                     ((l >> 3) & 1) * 16);

    // initial loads
    int sa = 0, sb;
    load_tile_async(su, g_xh + (size_t)i * 128 * DIM, tid);
    if (j != i) {
        load_tile_async(su + ATILE, g_xh + (size_t)j * 128 * DIM, tid);
        sb = 1;
    } else sb = 0;
    CPCOMMIT();

    float best[4] = {-2.0f, -2.0f, -2.0f, -2.0f};
    int   bidx[4] = {0, 0, 0, 0};
    float c_[2][8][4];

    #pragma unroll 1
    for (int n = 0; n < cnt; n++) {
        CPWAIT0();
        __syncthreads();

        int nsa = sa, nsb = sb, ii2 = i, jj2 = j;
        if (n + 1 < cnt) {
            int fs = free_slot(sa, sb);
            if (j + 1 < 64) {
                load_tile_async(su + fs * ATILE, g_xh + (size_t)(j + 1) * 128 * DIM, tid);
                nsb = fs; jj2 = j + 1;
            } else {
                load_tile_async(su + fs * ATILE, g_xh + (size_t)(i + 1) * 128 * DIM, tid);
                nsa = fs; nsb = fs; ii2 = i + 1; jj2 = i + 1;
            }
            CPCOMMIT();
        }

        mma_tile(c_, su + sa * ATILE, su + sb * ATILE, aoff, boff);
        fold_tile(c_, i, j, rloc, wn, l, best, bidx);
        if (n + 1 == cnt || ii2 != i)
            flush_rows(i, rloc, l, best, bidx);

        sa = nsa; sb = nsb; i = ii2; j = jj2;
    }
}

// ---------------------------------------------------------------------------
// Kernel 3: per-row distance + log + fused reduction. One warp per row.
__global__ void koleo_dist(const float* __restrict__ x, float* __restrict__ out) {
    __shared__ float sh[8];
    int row  = blockIdx.x * 8 + (threadIdx.x >> 5);
    int lane = threadIdx.x & 31;
    int nb   = unpack_idx(g_best[row]);
    float ii = g_inv[row];
    float ij = g_inv[nb];
    const float4* xi = (const float4*)(x + (size_t)row * DIM);
    const float4* xj = (const float4*)(x + (size_t)nb  * DIM);
    float s = 0.0f;
    #pragma unroll
    for (int c = 0; c < 2; c++) {
        float4 a = xi[lane + c * 32];
        float4 b = xj[lane + c * 32];
        float d0 = a.x * ii - b.x * ij + kEPS, d1 = a.y * ii - b.y * ij + kEPS;
        float d2 = a.z * ii - b.z * ij + kEPS, d3 = a.w * ii - b.w * ij + kEPS;
        s = fmaf(d0, d0, s); s = fmaf(d1, d1, s);
        s = fmaf(d2, d2, s); s = fmaf(d3, d3, s);
    }
    #pragma unroll
    for (int o = 16; o > 0; o >>= 1) s += __shfl_xor_sync(0xffffffffu, s, o);
    if (lane == 0) sh[threadIdx.x >> 5] = logf(sqrtf(s) + kEPS);
    __syncthreads();
    if (threadIdx.x == 0) {
        float t = sh[0] + sh[1] + sh[2] + sh[3] + sh[4] + sh[5] + sh[6] + sh[7];
        atomicAdd(out, t * (-1.0f / (float)BROWS));
    }
}

// ---------------------------------------------------------------------------
extern "C" void kernel_launch(void* const* d_in, const int* in_sizes, int n_in,
                              void* d_out, int out_size) {
    const float* student = (const float*)d_in[0];
    float* out = (float*)d_out;
    (void)in_sizes; (void)n_in; (void)out_size;

    const int smem_bytes = 3 * ATILE;      // 202752 B dynamic
    cudaFuncSetAttribute(koleo_gemm, cudaFuncAttributeMaxDynamicSharedMemorySize, smem_bytes);

    koleo_normcvt<<<BROWS / 8, 256>>>(student, out);
    koleo_gemm<<<NCTA, 256, smem_bytes>>>();
    koleo_dist<<<BROWS / 8, 256>>>(student, out);
}

// round 7
// speedup vs baseline: 11.6331x; 1.0757x over previous
#include <cuda_runtime.h>
#include <cuda_fp16.h>
#include <math.h>
#include <stdint.h>

#define BROWS 8192
#define DIM   256
#define RSB   528           // smem row stride bytes (256 halves + 8 pad)
#define ATILE (128 * RSB)   // 67584 B per tile slot
#define NCTA  148

static __device__ __constant__ float kEPS = 1e-8f;

// ------------------------- device scratch ----------------------------------
__device__ __align__(16) __half g_xh[BROWS * DIM];   // normalized fp16 (4 MB)
__device__ float                g_inv[BROWS];        // per-row 1/norm
__device__ unsigned long long   g_best[BROWS];

// ------------------------- helpers -----------------------------------------
__device__ __forceinline__ uint32_t smem_u32(const void* p) {
    uint32_t a;
    asm("{ .reg .u64 t; cvta.to.shared.u64 t, %1; cvt.u32.u64 %0, t; }" : "=r"(a) : "l"(p));
    return a;
}
__device__ __forceinline__ void ldsm4(uint32_t r[4], uint32_t a) {
    asm volatile("ldmatrix.sync.aligned.m8n8.x4.shared.b16 {%0,%1,%2,%3}, [%4];"
                 : "=r"(r[0]), "=r"(r[1]), "=r"(r[2]), "=r"(r[3]) : "r"(a));
}
__device__ __forceinline__ void mma16816(float c[4], const uint32_t a[4],
                                         uint32_t b0, uint32_t b1) {
    asm volatile("mma.sync.aligned.m16n8k16.row.col.f32.f16.f16.f32 "
                 "{%0,%1,%2,%3}, {%4,%5,%6,%7}, {%8,%9}, {%0,%1,%2,%3};"
                 : "+f"(c[0]), "+f"(c[1]), "+f"(c[2]), "+f"(c[3])
                 : "r"(a[0]), "r"(a[1]), "r"(a[2]), "r"(a[3]), "r"(b0), "r"(b1));
}
#define CP16(dst, src)  asm volatile("cp.async.cg.shared.global [%0], [%1], 16;" :: "r"(dst), "l"(src) : "memory")
#define CPCOMMIT()      asm volatile("cp.async.commit_group;" ::: "memory")
#define CPWAIT0()       asm volatile("cp.async.wait_group 0;" ::: "memory")

// pack: high 32 = orderable key (dot+2 > 0), low 32 = 8191-idx (tie -> smaller idx)
__device__ __forceinline__ unsigned long long pack_vi(float v, int idx) {
    return ((unsigned long long)__float_as_uint(v + 2.0f) << 32) |
           (unsigned)(8191 - idx);
}
__device__ __forceinline__ int unpack_idx(unsigned long long p) {
    return 8191 - (int)(p & 0xFFFFFFFFull);
}
__device__ __forceinline__ unsigned long long u64max(unsigned long long a,
                                                     unsigned long long b) {
    return a > b ? a : b;
}
__device__ __forceinline__ unsigned long long shfl_xor_u64(unsigned long long v, int m) {
    uint32_t lo = (uint32_t)v, hi = (uint32_t)(v >> 32);
    lo = __shfl_xor_sync(0xffffffffu, lo, m);
    hi = __shfl_xor_sync(0xffffffffu, hi, m);
    return ((unsigned long long)hi << 32) | lo;
}

// ---------------------------------------------------------------------------
// Kernel 1: normalize -> fp16 + inv-norm; zero g_best; zero out. 1 warp/row.
__global__ void koleo_normcvt(const float* __restrict__ x, float* __restrict__ out) {
    int row  = blockIdx.x * 8 + (threadIdx.x >> 5);
    int lane = threadIdx.x & 31;
    const float4* src = (const float4*)(x + (size_t)row * DIM);
    float4 v0 = src[lane];
    float4 v1 = src[lane + 32];
    float s = v0.x*v0.x + v0.y*v0.y + v0.z*v0.z + v0.w*v0.w
            + v1.x*v1.x + v1.y*v1.y + v1.z*v1.z + v1.w*v1.w;
    #pragma unroll
    for (int o = 16; o > 0; o >>= 1) s += __shfl_xor_sync(0xffffffffu, s, o);
    float inv = 1.0f / fmaxf(sqrtf(s), kEPS);
    v0.x *= inv; v0.y *= inv; v0.z *= inv; v0.w *= inv;
    v1.x *= inv; v1.y *= inv; v1.z *= inv; v1.w *= inv;

    ushort4 H0, H1;
    H0.x = __half_as_ushort(__float2half_rn(v0.x));
    H0.y = __half_as_ushort(__float2half_rn(v0.y));
    H0.z = __half_as_ushort(__float2half_rn(v0.z));
    H0.w = __half_as_ushort(__float2half_rn(v0.w));
    H1.x = __half_as_ushort(__float2half_rn(v1.x));
    H1.y = __half_as_ushort(__float2half_rn(v1.y));
    H1.z = __half_as_ushort(__float2half_rn(v1.z));
    H1.w = __half_as_ushort(__float2half_rn(v1.w));
    ushort4* hdst = (ushort4*)(g_xh + (size_t)row * DIM);
    hdst[lane] = H0; hdst[lane + 32] = H1;
    if (lane == 0) { g_inv[row] = inv; g_best[row] = 0ull; }
    if (blockIdx.x == 0 && threadIdx.x == 0) out[0] = 0.0f;
}

// ---------------------------------------------------------------------------
__device__ __forceinline__ void load_tile_async(uint32_t sdst,
                                                const __half* __restrict__ src,
                                                int tid) {
    #pragma unroll
    for (int i = 0; i < 8; i++) {
        int flat = tid + i * 512;
        int r = flat >> 5;
        int c = flat & 31;
        CP16(sdst + r * RSB + c * 16, src + (size_t)r * DIM + c * 8);
    }
}

// 32x32 warp tile: mi(2) x ni(4) x 4 accumulators
__device__ __forceinline__ void mma_tile(float (&c_)[2][4][4], uint32_t uA, uint32_t uB,
                                         uint32_t aoff, uint32_t boff) {
    #pragma unroll
    for (int mi = 0; mi < 2; mi++)
        #pragma unroll
        for (int ni = 0; ni < 4; ni++)
            #pragma unroll
            for (int q = 0; q < 4; q++) c_[mi][ni][q] = 0.0f;
    #pragma unroll
    for (int k = 0; k < 16; k++) {
        uint32_t a0[4], a1[4];
        ldsm4(a0, uA + aoff + k * 32);
        ldsm4(a1, uA + aoff + 16 * RSB + k * 32);
        uint32_t b[2][4];
        ldsm4(b[0], uB + boff + k * 32);
        ldsm4(b[1], uB + boff + 16 * RSB + k * 32);
        #pragma unroll
        for (int ni = 0; ni < 4; ni++) {
            uint32_t b0 = b[ni >> 1][(ni & 1) * 2];
            uint32_t b1 = b[ni >> 1][(ni & 1) * 2 + 1];
            mma16816(c_[0][ni], a0, b0, b1);
            mma16816(c_[1][ni], a1, b0, b1);
        }
    }
}

// fold tile (pi, pj): row-side into running best, column-side via REDG.
__device__ __forceinline__ void fold_tile(const float (&c_)[2][4][4], int pi, int pj,
                                          int rloc, int wn, int l,
                                          float best[4], int bidx[4]) {
    const int colb = pj * 128 + wn * 32 + (l & 3) * 2;
    const int rbase = pi * 128 + rloc;
    if (pi == pj) {
        #pragma unroll
        for (int mi = 0; mi < 2; mi++)
            #pragma unroll
            for (int h = 0; h < 2; h++) {
                const int bi = mi * 2 + h;
                const int row = rbase + mi * 16 + h * 8;
                #pragma unroll
                for (int ni = 0; ni < 4; ni++)
                    #pragma unroll
                    for (int bb = 0; bb < 2; bb++) {
                        float v = c_[mi][ni][h * 2 + bb];
                        int col = colb + ni * 8 + bb;
                        if (col == row) continue;
                        if (v > best[bi]) { best[bi] = v; bidx[bi] = col; }
                    }
            }
    } else {
        #pragma unroll
        for (int mi = 0; mi < 2; mi++)
            #pragma unroll
            for (int h = 0; h < 2; h++) {
                const int bi = mi * 2 + h;
                #pragma unroll
                for (int ni = 0; ni < 4; ni++)
                    #pragma unroll
                    for (int bb = 0; bb < 2; bb++) {
                        float v = c_[mi][ni][h * 2 + bb];
                        int col = colb + ni * 8 + bb;
                        if (v > best[bi]) { best[bi] = v; bidx[bi] = col; }
                    }
            }
        // column fold: per (ni,bb), max over (mi,h), lanes xor 4/8/16, REDG
        #pragma unroll
        for (int ni = 0; ni < 4; ni++)
            #pragma unroll
            for (int bb = 0; bb < 2; bb++) {
                float bv = c_[0][ni][bb];      int br = rbase;
                float v;
                v = c_[0][ni][2 + bb]; if (v > bv) { bv = v; br = rbase + 8;  }
                v = c_[1][ni][bb];     if (v > bv) { bv = v; br = rbase + 16; }
                v = c_[1][ni][2 + bb]; if (v > bv) { bv = v; br = rbase + 24; }
                unsigned long long p = pack_vi(bv, br);
                p = u64max(p, shfl_xor_u64(p, 4));
                p = u64max(p, shfl_xor_u64(p, 8));
                p = u64max(p, shfl_xor_u64(p, 16));
                if ((l >> 2) == 0)
                    atomicMax(&g_best[colb + ni * 8 + bb], p);
            }
    }
}

__device__ __forceinline__ void flush_rows(int rowblk, int rloc, int l,
                                           float best[4], int bidx[4]) {
    #pragma unroll
    for (int bi = 0; bi < 4; bi++) {
        unsigned long long p = pack_vi(best[bi], bidx[bi]);
        p = u64max(p, shfl_xor_u64(p, 1));
        p = u64max(p, shfl_xor_u64(p, 2));
        if ((l & 3) == 0) {
            int row = rowblk * 128 + rloc + (bi >> 1) * 16 + (bi & 1) * 8;
            atomicMax(&g_best[row], p);
        }
        best[bi] = -2.0f; bidx[bi] = 0;
    }
}

__device__ __forceinline__ int free_slot(int sa, int sb) {
    if (sa != 0 && sb != 0) return 0;
    if (sa != 1 && sb != 1) return 1;
    return 2;
}

// ---------------------------------------------------------------------------
// Kernel 2: persistent balanced upper-tri GEMM-argmax. 148 CTAs, 512 thr,
// 16 warps in a 4x4 grid of 32x32 warp tiles (fold overlaps MMA across warps).
__global__ void __launch_bounds__(512, 1) koleo_gemm() {
    extern __shared__ __align__(16) char smem[];
    const uint32_t su = smem_u32(smem);
    const int tid = threadIdx.x;
    const int l   = tid & 31;
    const int wid = tid >> 5;
    const int wm  = wid >> 2;            // 0..3 (M)
    const int wn  = wid & 3;             // 0..3 (N)
    const int rloc = wm * 32 + (l >> 2);
    const int b   = blockIdx.x;

    const int cnt = 14 + (b < 8 ? 1 : 0);
    int s = b * 14 + (b < 8 ? b : 8);
    int i = 0;
    while (s >= 64 - i) { s -= 64 - i; i++; }
    int j = i + s;

    const uint32_t aoff = (uint32_t)((wm * 32 + (l & 15)) * RSB + (l >> 4) * 16);
    const uint32_t boff = (uint32_t)((wn * 32 + (l & 7) + ((l >> 4) << 3)) * RSB +
                                     ((l >> 3) & 1) * 16);

    // initial loads
    int sa = 0, sb;
    load_tile_async(su, g_xh + (size_t)i * 128 * DIM, tid);
    if (j != i) {
        load_tile_async(su + ATILE, g_xh + (size_t)j * 128 * DIM, tid);
        sb = 1;
    } else sb = 0;
    CPCOMMIT();

    float best[4] = {-2.0f, -2.0f, -2.0f, -2.0f};
    int   bidx[4] = {0, 0, 0, 0};
    float c_[2][4][4];

    #pragma unroll 1
    for (int n = 0; n < cnt; n++) {
        CPWAIT0();
        __syncthreads();

        int nsa = sa, nsb = sb, ii2 = i, jj2 = j;
        if (n + 1 < cnt) {
            int fs = free_slot(sa, sb);
            if (j + 1 < 64) {
                load_tile_async(su + fs * ATILE, g_xh + (size_t)(j + 1) * 128 * DIM, tid);
                nsb = fs; jj2 = j + 1;
            } else {
                load_tile_async(su + fs * ATILE, g_xh + (size_t)(i + 1) * 128 * DIM, tid);
                nsa = fs; nsb = fs; ii2 = i + 1; jj2 = i + 1;
            }
            CPCOMMIT();
        }

        mma_tile(c_, su + sa * ATILE, su + sb * ATILE, aoff, boff);
        fold_tile(c_, i, j, rloc, wn, l, best, bidx);
        if (n + 1 == cnt || ii2 != i)
            flush_rows(i, rloc, l, best, bidx);

        sa = nsa; sb = nsb; i = ii2; j = jj2;
    }
}

// ---------------------------------------------------------------------------
// Kernel 3: per-row distance + log + fused reduction. One warp per row.
__global__ void koleo_dist(const float* __restrict__ x, float* __restrict__ out) {
    __shared__ float sh[8];
    int row  = blockIdx.x * 8 + (threadIdx.x >> 5);
    int lane = threadIdx.x & 31;
    int nb   = unpack_idx(g_best[row]);
    float ii = g_inv[row];
    float ij = g_inv[nb];
    const float4* xi = (const float4*)(x + (size_t)row * DIM);
    const float4* xj = (const float4*)(x + (size_t)nb  * DIM);
    float s = 0.0f;
    #pragma unroll
    for (int c = 0; c < 2; c++) {
        float4 a = xi[lane + c * 32];
        float4 b = xj[lane + c * 32];
        float d0 = a.x * ii - b.x * ij + kEPS, d1 = a.y * ii - b.y * ij + kEPS;
        float d2 = a.z * ii - b.z * ij + kEPS, d3 = a.w * ii - b.w * ij + kEPS;
        s = fmaf(d0, d0, s); s = fmaf(d1, d1, s);
        s = fmaf(d2, d2, s); s = fmaf(d3, d3, s);
    }
    #pragma unroll
    for (int o = 16; o > 0; o >>= 1) s += __shfl_xor_sync(0xffffffffu, s, o);
    if (lane == 0) sh[threadIdx.x >> 5] = logf(sqrtf(s) + kEPS);
    __syncthreads();
    if (threadIdx.x == 0) {
        float t = sh[0] + sh[1] + sh[2] + sh[3] + sh[4] + sh[5] + sh[6] + sh[7];
        atomicAdd(out, t * (-1.0f / (float)BROWS));
    }
}

// ---------------------------------------------------------------------------
extern "C" void kernel_launch(void* const* d_in, const int* in_sizes, int n_in,
                              void* d_out, int out_size) {
    const float* student = (const float*)d_in[0];
    float* out = (float*)d_out;
    (void)in_sizes; (void)n_in; (void)out_size;

    const int smem_bytes = 3 * ATILE;      // 202752 B dynamic
    cudaFuncSetAttribute(koleo_gemm, cudaFuncAttributeMaxDynamicSharedMemorySize, smem_bytes);

    koleo_normcvt<<<BROWS / 8, 256>>>(student, out);
    koleo_gemm<<<NCTA, 512, smem_bytes>>>();
    koleo_dist<<<BROWS / 8, 256>>>(student, out);
}

// round 8
// speedup vs baseline: 12.3525x; 1.0618x over previous
#include <cuda_runtime.h>
#include <cuda_fp16.h>
#include <math.h>
#include <stdint.h>

#define BROWS 8192
#define DIM   256
#define RSB   528           // smem row stride bytes (256 halves + 8 pad)
#define ATILE (128 * RSB)   // 67584 B per tile slot
#define NCTA  148

static __device__ __constant__ float kEPS = 1e-8f;

// ------------------------- device scratch ----------------------------------
__device__ __align__(16) __half g_xh[BROWS * DIM];   // normalized fp16 (4 MB)
__device__ float                g_inv[BROWS];        // per-row 1/norm
__device__ unsigned long long   g_best[BROWS];

// ------------------------- helpers -----------------------------------------
__device__ __forceinline__ uint32_t smem_u32(const void* p) {
    uint32_t a;
    asm("{ .reg .u64 t; cvta.to.shared.u64 t, %1; cvt.u32.u64 %0, t; }" : "=r"(a) : "l"(p));
    return a;
}
__device__ __forceinline__ void ldsm4(uint32_t r[4], uint32_t a) {
    asm volatile("ldmatrix.sync.aligned.m8n8.x4.shared.b16 {%0,%1,%2,%3}, [%4];"
                 : "=r"(r[0]), "=r"(r[1]), "=r"(r[2]), "=r"(r[3]) : "r"(a));
}
// fp16-accumulate MMA: D,C are 2 regs (4 halves)
__device__ __forceinline__ void mma16816h(uint32_t c[2], const uint32_t a[4],
                                          uint32_t b0, uint32_t b1) {
    asm volatile("mma.sync.aligned.m16n8k16.row.col.f16.f16.f16.f16 "
                 "{%0,%1}, {%2,%3,%4,%5}, {%6,%7}, {%0,%1};"
                 : "+r"(c[0]), "+r"(c[1])
                 : "r"(a[0]), "r"(a[1]), "r"(a[2]), "r"(a[3]), "r"(b0), "r"(b1));
}
#define CP16(dst, src)  asm volatile("cp.async.cg.shared.global [%0], [%1], 16;" :: "r"(dst), "l"(src) : "memory")
#define CPCOMMIT()      asm volatile("cp.async.commit_group;" ::: "memory")
#define CPWAIT0()       asm volatile("cp.async.wait_group 0;" ::: "memory")

// pack: high 32 = orderable key (dot+2 > 0), low 32 = 8191-idx (tie -> smaller idx)
__device__ __forceinline__ unsigned long long pack_vi(float v, int idx) {
    return ((unsigned long long)__float_as_uint(v + 2.0f) << 32) |
           (unsigned)(8191 - idx);
}
__device__ __forceinline__ int unpack_idx(unsigned long long p) {
    return 8191 - (int)(p & 0xFFFFFFFFull);
}
__device__ __forceinline__ unsigned long long u64max(unsigned long long a,
                                                     unsigned long long b) {
    return a > b ? a : b;
}
__device__ __forceinline__ unsigned long long shfl_xor_u64(unsigned long long v, int m) {
    uint32_t lo = (uint32_t)v, hi = (uint32_t)(v >> 32);
    lo = __shfl_xor_sync(0xffffffffu, lo, m);
    hi = __shfl_xor_sync(0xffffffffu, hi, m);
    return ((unsigned long long)hi << 32) | lo;
}

// ---------------------------------------------------------------------------
// Kernel 1: normalize -> fp16 + inv-norm; zero g_best; zero out. 1 warp/row.
__global__ void koleo_normcvt(const float* __restrict__ x, float* __restrict__ out) {
    int row  = blockIdx.x * 8 + (threadIdx.x >> 5);
    int lane = threadIdx.x & 31;
    const float4* src = (const float4*)(x + (size_t)row * DIM);
    float4 v0 = src[lane];
    float4 v1 = src[lane + 32];
    float s = v0.x*v0.x + v0.y*v0.y + v0.z*v0.z + v0.w*v0.w
            + v1.x*v1.x + v1.y*v1.y + v1.z*v1.z + v1.w*v1.w;
    #pragma unroll
    for (int o = 16; o > 0; o >>= 1) s += __shfl_xor_sync(0xffffffffu, s, o);
    float inv = 1.0f / fmaxf(sqrtf(s), kEPS);
    v0.x *= inv; v0.y *= inv; v0.z *= inv; v0.w *= inv;
    v1.x *= inv; v1.y *= inv; v1.z *= inv; v1.w *= inv;

    ushort4 H0, H1;
    H0.x = __half_as_ushort(__float2half_rn(v0.x));
    H0.y = __half_as_ushort(__float2half_rn(v0.y));
    H0.z = __half_as_ushort(__float2half_rn(v0.z));
    H0.w = __half_as_ushort(__float2half_rn(v0.w));
    H1.x = __half_as_ushort(__float2half_rn(v1.x));
    H1.y = __half_as_ushort(__float2half_rn(v1.y));
    H1.z = __half_as_ushort(__float2half_rn(v1.z));
    H1.w = __half_as_ushort(__float2half_rn(v1.w));
    ushort4* hdst = (ushort4*)(g_xh + (size_t)row * DIM);
    hdst[lane] = H0; hdst[lane + 32] = H1;
    if (lane == 0) { g_inv[row] = inv; g_best[row] = 0ull; }
    if (blockIdx.x == 0 && threadIdx.x == 0) out[0] = 0.0f;
}

// ---------------------------------------------------------------------------
// 32x32 warp tile, fp16 accumulators: c_[mi][ni][2] (half2 pairs).
// Prefetch of the next tile is interleaved into the k-loop (k=4..11),
// one cp.async per thread per step, so LDGSTS issue hides under HMMA.
__device__ __forceinline__ void mma_tile(uint32_t (&c_)[2][4][2], uint32_t uA, uint32_t uB,
                                         uint32_t aoff, uint32_t boff,
                                         bool pf, uint32_t pfdst,
                                         const __half* __restrict__ pfsrc, int tid) {
    #pragma unroll
    for (int mi = 0; mi < 2; mi++)
        #pragma unroll
        for (int ni = 0; ni < 4; ni++) { c_[mi][ni][0] = 0u; c_[mi][ni][1] = 0u; }
    #pragma unroll
    for (int k = 0; k < 16; k++) {
        if (k >= 4 && k < 12 && pf) {
            int flat = tid + (k - 4) * 512;
            int r = flat >> 5;
            int c = flat & 31;
            CP16(pfdst + r * RSB + c * 16, pfsrc + (size_t)r * DIM + c * 8);
        }
        uint32_t a0[4], a1[4];
        ldsm4(a0, uA + aoff + k * 32);
        ldsm4(a1, uA + aoff + 16 * RSB + k * 32);
        uint32_t b[2][4];
        ldsm4(b[0], uB + boff + k * 32);
        ldsm4(b[1], uB + boff + 16 * RSB + k * 32);
        #pragma unroll
        for (int ni = 0; ni < 4; ni++) {
            uint32_t b0 = b[ni >> 1][(ni & 1) * 2];
            uint32_t b1 = b[ni >> 1][(ni & 1) * 2 + 1];
            mma16816h(c_[0][ni], a0, b0, b1);
            mma16816h(c_[1][ni], a1, b0, b1);
        }
    }
}

// fold tile (pi, pj): row-side into running best, column-side via REDG.
__device__ __forceinline__ void fold_tile(const uint32_t (&c_)[2][4][2], int pi, int pj,
                                          int rloc, int wn, int l,
                                          float best[4], int bidx[4]) {
    const int colb = pj * 128 + wn * 32 + (l & 3) * 2;
    const int rbase = pi * 128 + rloc;
    float f[2][4][4];
    #pragma unroll
    for (int mi = 0; mi < 2; mi++)
        #pragma unroll
        for (int ni = 0; ni < 4; ni++) {
            float2 lo = __half22float2(*(const __half2*)&c_[mi][ni][0]);
            float2 hi = __half22float2(*(const __half2*)&c_[mi][ni][1]);
            f[mi][ni][0] = lo.x; f[mi][ni][1] = lo.y;
            f[mi][ni][2] = hi.x; f[mi][ni][3] = hi.y;
        }
    if (pi == pj) {
        #pragma unroll
        for (int mi = 0; mi < 2; mi++)
            #pragma unroll
            for (int h = 0; h < 2; h++) {
                const int bi = mi * 2 + h;
                const int row = rbase + mi * 16 + h * 8;
                #pragma unroll
                for (int ni = 0; ni < 4; ni++)
                    #pragma unroll
                    for (int bb = 0; bb < 2; bb++) {
                        float v = f[mi][ni][h * 2 + bb];
                        int col = colb + ni * 8 + bb;
                        if (col == row) continue;
                        if (v > best[bi]) { best[bi] = v; bidx[bi] = col; }
                    }
            }
    } else {
        #pragma unroll
        for (int mi = 0; mi < 2; mi++)
            #pragma unroll
            for (int h = 0; h < 2; h++) {
                const int bi = mi * 2 + h;
                #pragma unroll
                for (int ni = 0; ni < 4; ni++)
                    #pragma unroll
                    for (int bb = 0; bb < 2; bb++) {
                        float v = f[mi][ni][h * 2 + bb];
                        int col = colb + ni * 8 + bb;
                        if (v > best[bi]) { best[bi] = v; bidx[bi] = col; }
                    }
            }
        // column fold: per (ni,bb), max over (mi,h), lanes xor 4/8/16, REDG
        #pragma unroll
        for (int ni = 0; ni < 4; ni++)
            #pragma unroll
            for (int bb = 0; bb < 2; bb++) {
                float bv = f[0][ni][bb];       int br = rbase;
                float v;
                v = f[0][ni][2 + bb]; if (v > bv) { bv = v; br = rbase + 8;  }
                v = f[1][ni][bb];     if (v > bv) { bv = v; br = rbase + 16; }
                v = f[1][ni][2 + bb]; if (v > bv) { bv = v; br = rbase + 24; }
                unsigned long long p = pack_vi(bv, br);
                p = u64max(p, shfl_xor_u64(p, 4));
                p = u64max(p, shfl_xor_u64(p, 8));
                p = u64max(p, shfl_xor_u64(p, 16));
                if ((l >> 2) == 0)
                    atomicMax(&g_best[colb + ni * 8 + bb], p);
            }
    }
}

__device__ __forceinline__ void flush_rows(int rowblk, int rloc, int l,
                                           float best[4], int bidx[4]) {
    #pragma unroll
    for (int bi = 0; bi < 4; bi++) {
        unsigned long long p = pack_vi(best[bi], bidx[bi]);
        p = u64max(p, shfl_xor_u64(p, 1));
        p = u64max(p, shfl_xor_u64(p, 2));
        if ((l & 3) == 0) {
            int row = rowblk * 128 + rloc + (bi >> 1) * 16 + (bi & 1) * 8;
            atomicMax(&g_best[row], p);
        }
        best[bi] = -2.0f; bidx[bi] = 0;
    }
}

__device__ __forceinline__ int free_slot(int sa, int sb) {
    if (sa != 0 && sb != 0) return 0;
    if (sa != 1 && sb != 1) return 1;
    return 2;
}

// ---------------------------------------------------------------------------
// Kernel 2: persistent balanced upper-tri GEMM-argmax. 148 CTAs, 512 thr,
// 16 warps in a 4x4 grid of 32x32 warp tiles.
__global__ void __launch_bounds__(512, 1) koleo_gemm() {
    extern __shared__ __align__(16) char smem[];
    const uint32_t su = smem_u32(smem);
    const int tid = threadIdx.x;
    const int l   = tid & 31;
    const int wid = tid >> 5;
    const int wm  = wid >> 2;            // 0..3 (M)
    const int wn  = wid & 3;             // 0..3 (N)
    const int rloc = wm * 32 + (l >> 2);
    const int b   = blockIdx.x;

    const int cnt = 14 + (b < 8 ? 1 : 0);
    int s = b * 14 + (b < 8 ? b : 8);
    int i = 0;
    while (s >= 64 - i) { s -= 64 - i; i++; }
    int j = i + s;

    const uint32_t aoff = (uint32_t)((wm * 32 + (l & 15)) * RSB + (l >> 4) * 16);
    const uint32_t boff = (uint32_t)((wn * 32 + (l & 7) + ((l >> 4) << 3)) * RSB +
                                     ((l >> 3) & 1) * 16);

    // initial loads (full tiles, outside the pipeline)
    int sa = 0, sb;
    #pragma unroll
    for (int q = 0; q < 8; q++) {
        int flat = tid + q * 512;
        int r = flat >> 5;
        int c = flat & 31;
        CP16(su + r * RSB + c * 16, g_xh + (size_t)i * 128 * DIM + (size_t)r * DIM + c * 8);
    }
    if (j != i) {
        #pragma unroll
        for (int q = 0; q < 8; q++) {
            int flat = tid + q * 512;
            int r = flat >> 5;
            int c = flat & 31;
            CP16(su + ATILE + r * RSB + c * 16,
                 g_xh + (size_t)j * 128 * DIM + (size_t)r * DIM + c * 8);
        }
        sb = 1;
    } else sb = 0;
    CPCOMMIT();

    float best[4] = {-2.0f, -2.0f, -2.0f, -2.0f};
    int   bidx[4] = {0, 0, 0, 0};
    uint32_t c_[2][4][2];

    #pragma unroll 1
    for (int n = 0; n < cnt; n++) {
        CPWAIT0();
        __syncthreads();

        int nsa = sa, nsb = sb, ii2 = i, jj2 = j;
        bool pf = (n + 1 < cnt);
        uint32_t pfdst = 0;
        const __half* pfsrc = nullptr;
        if (pf) {
            int fs = free_slot(sa, sb);
            pfdst = su + fs * ATILE;
            if (j + 1 < 64) {
                pfsrc = g_xh + (size_t)(j + 1) * 128 * DIM;
                nsb = fs; jj2 = j + 1;
            } else {
                pfsrc = g_xh + (size_t)(i + 1) * 128 * DIM;
                nsa = fs; nsb = fs; ii2 = i + 1; jj2 = i + 1;
            }
        }

        mma_tile(c_, su + sa * ATILE, su + sb * ATILE, aoff, boff, pf, pfdst, pfsrc, tid);
        if (pf) CPCOMMIT();
        fold_tile(c_, i, j, rloc, wn, l, best, bidx);
        if (n + 1 == cnt || ii2 != i)
            flush_rows(i, rloc, l, best, bidx);

        sa = nsa; sb = nsb; i = ii2; j = jj2;
    }
}

// ---------------------------------------------------------------------------
// Kernel 3: per-row distance + log + fused reduction. One warp per row.
__global__ void koleo_dist(const float* __restrict__ x, float* __restrict__ out) {
    __shared__ float sh[8];
    int row  = blockIdx.x * 8 + (threadIdx.x >> 5);
    int lane = threadIdx.x & 31;
    int nb   = unpack_idx(g_best[row]);
    float ii = g_inv[row];
    float ij = g_inv[nb];
    const float4* xi = (const float4*)(x + (size_t)row * DIM);
    const float4* xj = (const float4*)(x + (size_t)nb  * DIM);
    float s = 0.0f;
    #pragma unroll
    for (int c = 0; c < 2; c++) {
        float4 a = xi[lane + c * 32];
        float4 b = xj[lane + c * 32];
        float d0 = a.x * ii - b.x * ij + kEPS, d1 = a.y * ii - b.y * ij + kEPS;
        float d2 = a.z * ii - b.z * ij + kEPS, d3 = a.w * ii - b.w * ij + kEPS;
        s = fmaf(d0, d0, s); s = fmaf(d1, d1, s);
        s = fmaf(d2, d2, s); s = fmaf(d3, d3, s);
    }
    #pragma unroll
    for (int o = 16; o > 0; o >>= 1) s += __shfl_xor_sync(0xffffffffu, s, o);
    if (lane == 0) sh[threadIdx.x >> 5] = logf(sqrtf(s) + kEPS);
    __syncthreads();
    if (threadIdx.x == 0) {
        float t = sh[0] + sh[1] + sh[2] + sh[3] + sh[4] + sh[5] + sh[6] + sh[7];
        atomicAdd(out, t * (-1.0f / (float)BROWS));
    }
}

// ---------------------------------------------------------------------------
extern "C" void kernel_launch(void* const* d_in, const int* in_sizes, int n_in,
                              void* d_out, int out_size) {
    const float* student = (const float*)d_in[0];
    float* out = (float*)d_out;
    (void)in_sizes; (void)n_in; (void)out_size;

    const int smem_bytes = 3 * ATILE;      // 202752 B dynamic
    cudaFuncSetAttribute(koleo_gemm, cudaFuncAttributeMaxDynamicSharedMemorySize, smem_bytes);

    koleo_normcvt<<<BROWS / 8, 256>>>(student, out);
    koleo_gemm<<<NCTA, 512, smem_bytes>>>();
    koleo_dist<<<BROWS / 8, 256>>>(student, out);
}